// round 17
// baseline (speedup 1.0000x reference)
#include <cuda_runtime.h>
#include <cstdint>

#define BATCH    64
#define LSEQ     16384
#define FCH      128
#define KW       16
#define OUT_LEN  16369            // (16384 - 16) + 1
#define TILE_O   256              // o per tile (2 og-groups x 8 subtiles of 16)
#define NTHREADS 256              // 8 warps: og = wid>>2 (0..1), fg = wid&3
#define NSUB     8                // subtiles per warp
#define XWIN     (TILE_O + KW - 1)  // 271
#define TILES_PER_B ((OUT_LEN + TILE_O - 1) / TILE_O)    // 64
#define NTILES   (BATCH * TILES_PER_B)                   // 4096
#define NCTAS    444              // 148 SMs x 3 resident CTAs

// split v into tf32 hi + tf32 lo (3xTF32 emulation parts)
__device__ __forceinline__ void split_tf32(float v, uint32_t& hi, uint32_t& lo) {
    uint32_t h;
    asm("cvt.rna.tf32.f32 %0, %1;" : "=r"(h) : "f"(v));
    float rem = v - __uint_as_float(h);      // tf32 bits are valid fp32
    uint32_t l;
    asm("cvt.rna.tf32.f32 %0, %1;" : "=r"(l) : "f"(rem));
    hi = h; lo = l;
}

// D(16x8) += A(16x8) * B(8x8)^T  -- tf32 inputs, fp32 accumulate
__device__ __forceinline__ void mma_16n8k8(float c[4], const uint32_t a[4],
                                           const uint32_t b[2]) {
    asm volatile(
        "mma.sync.aligned.m16n8k8.row.col.f32.tf32.tf32.f32 "
        "{%0,%1,%2,%3}, {%4,%5,%6,%7}, {%8,%9}, {%0,%1,%2,%3};"
        : "+f"(c[0]), "+f"(c[1]), "+f"(c[2]), "+f"(c[3])
        : "r"(a[0]), "r"(a[1]), "r"(a[2]), "r"(a[3]), "r"(b[0]), "r"(b[1]));
}

__device__ __forceinline__ float relu_(float v) { return fmaxf(v, 0.0f); }

// streaming (evict-first) 128-bit store
__device__ __forceinline__ void stg_cs_v4(float* p, float a, float b,
                                          float c, float d) {
    asm volatile("st.global.cs.v4.f32 [%0], {%1, %2, %3, %4};"
                 :: "l"(p), "f"(a), "f"(b), "f"(c), "f"(d) : "memory");
}

__global__ __launch_bounds__(NTHREADS, 2)
void speccnn1d_mma_kernel(const float* __restrict__ x,
                          const float* __restrict__ kern,
                          float* __restrict__ out) {
    __shared__ uint32_t xs_hi[XWIN];
    __shared__ uint32_t xs_lo[XWIN];

    const int tid  = threadIdx.x;
    const int lane = tid & 31;
    const int wid  = tid >> 5;

    const int fg = wid & 3;                  // f-group: 32 channels
    const int og = wid >> 2;                 // o-group: 128 rows (8 subtiles)
    const int t  = lane & 3;                 // threadID in group
    const int g  = lane >> 2;                // groupID

    // ---- B fragments, 3xTF32 split, sector-contiguous f permutation ----
    // Loaded ONCE per CTA (444 CTAs total, not 4096).
    // Block nb, fragment n-index n holds logical
    //   f = fg*32 + 16*(nb>>1) + 4*(n>>1) + 2*(nb&1) + (n&1)   (bijective)
    // => thread t's two float4s are f = fg*32+4t.. and fg*32+16+4t..;
    //    quad t=0..3 covers 64B contiguous per STG.128 (full sectors/lines).
    uint32_t Bb[4][2][2], Bs[4][2][2];
    #pragma unroll
    for (int nb = 0; nb < 4; nb++) {
        const int frow = fg * 32 + 16 * (nb >> 1) + 4 * (g >> 1)
                       + 2 * (nb & 1) + (g & 1);
        const float* wr = kern + (size_t)frow * KW;
        #pragma unroll
        for (int k = 0; k < 2; k++) {
            split_tf32(__ldg(&wr[k * 8 + t]),     Bb[nb][k][0], Bs[nb][k][0]);
            split_tf32(__ldg(&wr[k * 8 + t + 4]), Bb[nb][k][1], Bs[nb][k][1]);
        }
    }

    // ---- persistent loop over tiles ----
    for (int tile = blockIdx.x; tile < NTILES; tile += NCTAS) {
        const int b  = tile / TILES_PER_B;
        const int o0 = (tile - b * TILES_PER_B) * TILE_O;

        // ---- stage x window, pre-split into tf32 hi/lo ----
        {
            const float* xb = x + (size_t)b * LSEQ;
            #pragma unroll
            for (int i = tid; i < XWIN; i += NTHREADS) {
                int xi = o0 + i;
                float v = (xi < LSEQ) ? __ldg(&xb[xi]) : 0.0f;
                uint32_t h, l;
                split_tf32(v, h, l);
                xs_hi[i] = h;
                xs_lo[i] = l;
            }
        }
        __syncthreads();

        float* outb = out + (size_t)b * OUT_LEN * FCH + fg * 32;

        // ---- 8 o-subtiles of 16 per warp ----
        #pragma unroll
        for (int sub = 0; sub < NSUB; sub++) {
            const int obase = og * (16 * NSUB) + sub * 16;

            float C[4][4];
            #pragma unroll
            for (int nb = 0; nb < 4; nb++)
                #pragma unroll
                for (int j = 0; j < 4; j++) C[nb][j] = 0.0f;

            #pragma unroll
            for (int k = 0; k < 2; k++) {
                const int base = obase + g;
                const int kc   = k * 8 + t;
                uint32_t Ab[4], Al[4];
                Ab[0] = xs_hi[base + kc];          Al[0] = xs_lo[base + kc];
                Ab[1] = xs_hi[base + 8 + kc];      Al[1] = xs_lo[base + 8 + kc];
                Ab[2] = xs_hi[base + kc + 4];      Al[2] = xs_lo[base + kc + 4];
                Ab[3] = xs_hi[base + 8 + kc + 4];  Al[3] = xs_lo[base + 8 + kc + 4];

                #pragma unroll
                for (int nb = 0; nb < 4; nb++) {
                    mma_16n8k8(C[nb], Ab, Bb[nb][k]);   // big * big
                    mma_16n8k8(C[nb], Ab, Bs[nb][k]);   // big * small
                    mma_16n8k8(C[nb], Al, Bb[nb][k]);   // small * big
                }
            }

            // ---- epilogue: relu + 2x sector-contiguous streaming STG.128 ----
            const int r0 = o0 + obase + g;
            float* orow = outb + (size_t)r0 * FCH;

            if (r0 < OUT_LEN) {
                stg_cs_v4(orow + 4 * t,
                          relu_(C[0][0]), relu_(C[0][1]),
                          relu_(C[1][0]), relu_(C[1][1]));
                stg_cs_v4(orow + 16 + 4 * t,
                          relu_(C[2][0]), relu_(C[2][1]),
                          relu_(C[3][0]), relu_(C[3][1]));
            }
            if (r0 + 8 < OUT_LEN) {
                float* orow2 = orow + (size_t)8 * FCH;
                stg_cs_v4(orow2 + 4 * t,
                          relu_(C[0][2]), relu_(C[0][3]),
                          relu_(C[1][2]), relu_(C[1][3]));
                stg_cs_v4(orow2 + 16 + 4 * t,
                          relu_(C[2][2]), relu_(C[2][3]),
                          relu_(C[3][2]), relu_(C[3][3]));
            }
        }
        __syncthreads();    // protect xs_* against next iteration's staging
    }
}

extern "C" void kernel_launch(void* const* d_in, const int* in_sizes, int n_in,
                              void* d_out, int out_size) {
    const float* x    = (const float*)d_in[0];   // (64, 16384) fp32
    const float* kern = (const float*)d_in[1];   // (128, 16)  fp32
    float* out        = (float*)d_out;           // (64, 16369, 128) fp32

    speccnn1d_mma_kernel<<<NCTAS, NTHREADS>>>(x, kern, out);
}